// round 7
// baseline (speedup 1.0000x reference)
#include <cuda_runtime.h>

// SSIM-style loss (sum over channels+window, /ws^2), single fused kernel.
// x, y: (32, 3, 512, 512) fp32. out: (32,) fp32.
//
// 256-bit loads (Blackwell LDG.E.256): thread = (row-parity r, 32B-col u).
// Each thread streams 8 rows x 3 channels per input as ld.global.nc.v8.f32.
// Warp = 32 consecutive u -> 1024B fully-coalesced request.
// Window fold: shfl-xor(1) over u-pairs (two float8 = one 16-col window),
// smem combine across row parity, SSIM, warp fold, ticket finalize.

#define IMG_H 512
#define IMG_W 512
#define NCH 3
#define WS 16
#define NWIN_X 32
#define NWIN_Y 32
#define NBATCH 32
#define W8 (IMG_W / 8)          // 64 float8 per row

static __device__ float        g_partial[NBATCH * NWIN_Y];
static __device__ unsigned int g_ticket[NBATCH];

__device__ __forceinline__ void ldg256(const float* __restrict__ p, float v[8]) {
    asm volatile("ld.global.nc.v8.f32 {%0,%1,%2,%3,%4,%5,%6,%7}, [%8];"
                 : "=f"(v[0]), "=f"(v[1]), "=f"(v[2]), "=f"(v[3]),
                   "=f"(v[4]), "=f"(v[5]), "=f"(v[6]), "=f"(v[7])
                 : "l"(p));
}

__global__ __launch_bounds__(128, 7)
void ssim_fused_kernel(const float* __restrict__ x, const float* __restrict__ y,
                       float* __restrict__ out) {
    const int tid = threadIdx.x;
    const int r   = tid >> 6;              // row parity: rows r, r+2, ..., r+14
    const int u   = tid & 63;              // float8 column 0..63
    const int br  = blockIdx.x & 31;       // window row
    const int b   = blockIdx.x >> 5;       // batch

    const size_t img = (size_t)NCH * IMG_H * IMG_W;
    const float* __restrict__ xb = x + (size_t)b * img;
    const float* __restrict__ yb = y + (size_t)b * img;

    float sx = 0.f, sy = 0.f, sxx = 0.f, syy = 0.f, sxy = 0.f;

#pragma unroll
    for (int c = 0; c < NCH; ++c) {
        // element offset of (channel c, row br*16 + r, col 8u)
        size_t base = (size_t)c * (IMG_H * IMG_W)
                    + (size_t)(br * WS + r) * IMG_W + (size_t)(u << 3);
#pragma unroll
        for (int h = 0; h < 8; ++h) {       // rows r, r+2, ..., r+14
            const size_t off = base + (size_t)(h * 2) * IMG_W;
            float vx[8], vy[8];
            ldg256(xb + off, vx);
            ldg256(yb + off, vy);
#pragma unroll
            for (int j = 0; j < 8; ++j) {
                sx += vx[j];
                sy += vy[j];
                sxx = fmaf(vx[j], vx[j], sxx);
                syy = fmaf(vy[j], vy[j], syy);
                sxy = fmaf(vx[j], vy[j], sxy);
            }
        }
    }

    // fold u-pairs: lanes (u even, u odd) together hold one 16-col window
    sx  += __shfl_xor_sync(0xffffffffu, sx,  1);
    sy  += __shfl_xor_sync(0xffffffffu, sy,  1);
    sxx += __shfl_xor_sync(0xffffffffu, sxx, 1);
    syy += __shfl_xor_sync(0xffffffffu, syy, 1);
    sxy += __shfl_xor_sync(0xffffffffu, sxy, 1);

    // combine across row parity via smem: s_sums[r][window][5]
    __shared__ float s_sums[2][NWIN_X][5];
    __shared__ unsigned int s_ticket;
    if ((u & 1) == 0) {
        const int win = u >> 1;            // 0..31
        s_sums[r][win][0] = sx;
        s_sums[r][win][1] = sy;
        s_sums[r][win][2] = sxx;
        s_sums[r][win][3] = syy;
        s_sums[r][win][4] = sxy;
    }
    __syncthreads();

    if (tid < 32) {
        float S0 = s_sums[0][tid][0] + s_sums[1][tid][0];
        float S1 = s_sums[0][tid][1] + s_sums[1][tid][1];
        float S2 = s_sums[0][tid][2] + s_sums[1][tid][2];
        float S3 = s_sums[0][tid][3] + s_sums[1][tid][3];
        float S4 = s_sums[0][tid][4] + s_sums[1][tid][4];

        const float inv = 1.0f / (WS * WS);
        const float C1 = 6.5025f;
        const float C2 = 58.5225f;
        float mx = S0 * inv, my = S1 * inv;
        float vx = S2 * inv - mx * mx;
        float vy = S3 * inv - my * my;
        float cv = S4 * inv - mx * my;
        float num = (2.0f * mx * my + C1) * (2.0f * cv + C2);
        float den = (mx * mx + my * my + C1) * (vx + vy + C2);
        float v = num / den;

#pragma unroll
        for (int off = 16; off; off >>= 1)
            v += __shfl_xor_sync(0xffffffffu, v, off);
        if (tid == 0) {
            g_partial[blockIdx.x] = v;
            __threadfence();
            unsigned int tk = atomicAdd(&g_ticket[b], 1u);
            s_ticket = tk;
        }
    }
    __syncthreads();

    // Last CTA of this batch folds the 32 row-partials.
    if (s_ticket == NWIN_Y - 1) {
        if (tid < 32) {
            volatile float* vp = (volatile float*)&g_partial[b * NWIN_Y];
            float v = vp[tid];
#pragma unroll
            for (int off = 16; off; off >>= 1)
                v += __shfl_xor_sync(0xffffffffu, v, off);
            if (tid == 0) {
                out[b] = (1.0f - v * (1.0f / (NWIN_X * NWIN_Y))) * 0.5f;
                g_ticket[b] = 0u;   // reset for next (graph-replayed) launch
            }
        }
    }
}

extern "C" void kernel_launch(void* const* d_in, const int* in_sizes, int n_in,
                              void* d_out, int out_size) {
    const float* x = (const float*)d_in[0];
    const float* y = (const float*)d_in[1];
    float* out = (float*)d_out;
    (void)in_sizes; (void)n_in; (void)out_size;

    ssim_fused_kernel<<<NBATCH * NWIN_Y, 128>>>(x, y, out);
}

// round 8
// speedup vs baseline: 1.0072x; 1.0072x over previous
#include <cuda_runtime.h>

// SSIM-style loss (sum over channels+window, /ws^2), single fused kernel.
// x, y: (32, 3, 512, 512) fp32. out: (32,) fp32.
//
// FINAL (roofline-verified): 5 independent levers (MLP depth, occupancy
// 39-80%, cache policy, stream separation, 128/256-bit requests) all land
// at ~6.0 TB/s DRAM — the chip's effective fp32 streaming ceiling at NAT.
// This is the best-measured shape (R5): grid 1024 = (batch, window-row),
// 256 threads = (row-half, float4-col), 32 regs, one wave at 7+ CTA/SM.
// Epilogue micro-trim: release-scoped ticket atomic replaces
// __threadfence + relaxed atomic; acquire-read on the last-CTA fold.

#define IMG_H 512
#define IMG_W 512
#define NCH 3
#define WS 16
#define NWIN_X 32
#define NWIN_Y 32
#define NBATCH 32
#define W4 (IMG_W / 4)

static __device__ float        g_partial[NBATCH * NWIN_Y];
static __device__ unsigned int g_ticket[NBATCH];

__device__ __forceinline__ unsigned int atom_add_release(unsigned int* p, unsigned int v) {
    unsigned int old;
    asm volatile("atom.release.gpu.global.add.u32 %0, [%1], %2;"
                 : "=r"(old) : "l"(p), "r"(v) : "memory");
    return old;
}

__device__ __forceinline__ float ld_acquire_f32(const float* p) {
    float v;
    asm volatile("ld.acquire.gpu.global.f32 %0, [%1];" : "=f"(v) : "l"(p) : "memory");
    return v;
}

__global__ __launch_bounds__(256, 7)
void ssim_fused_kernel(const float* __restrict__ x, const float* __restrict__ y,
                       float* __restrict__ out) {
    const int tid = threadIdx.x;
    const int hh  = tid >> 7;              // row half: 0 -> rows 0..7, 1 -> rows 8..15
    const int t   = tid & 127;             // float4 column 0..127
    const int br  = blockIdx.x & 31;       // window row
    const int b   = blockIdx.x >> 5;       // batch

    const size_t img = (size_t)NCH * IMG_H * IMG_W;
    const float4* __restrict__ xp = (const float4*)(x + (size_t)b * img);
    const float4* __restrict__ yp = (const float4*)(y + (size_t)b * img);

    float sx = 0.f, sy = 0.f, sxx = 0.f, syy = 0.f, sxy = 0.f;

#pragma unroll
    for (int c = 0; c < NCH; ++c) {
        size_t base = (size_t)c * (IMG_H * W4)
                    + (size_t)(br * WS + hh * 8) * W4 + t;
#pragma unroll
        for (int h0 = 0; h0 < 8; h0 += 2) {
            float4 vx0 = __ldcs(xp + base + (size_t)(h0    ) * W4);
            float4 vx1 = __ldcs(xp + base + (size_t)(h0 + 1) * W4);
            float4 vy0 = __ldcs(yp + base + (size_t)(h0    ) * W4);
            float4 vy1 = __ldcs(yp + base + (size_t)(h0 + 1) * W4);

            sx += (vx0.x + vx0.y) + (vx0.z + vx0.w);
            sy += (vy0.x + vy0.y) + (vy0.z + vy0.w);
            sxx = fmaf(vx0.x, vx0.x, sxx); sxx = fmaf(vx0.y, vx0.y, sxx);
            sxx = fmaf(vx0.z, vx0.z, sxx); sxx = fmaf(vx0.w, vx0.w, sxx);
            syy = fmaf(vy0.x, vy0.x, syy); syy = fmaf(vy0.y, vy0.y, syy);
            syy = fmaf(vy0.z, vy0.z, syy); syy = fmaf(vy0.w, vy0.w, syy);
            sxy = fmaf(vx0.x, vy0.x, sxy); sxy = fmaf(vx0.y, vy0.y, sxy);
            sxy = fmaf(vx0.z, vy0.z, sxy); sxy = fmaf(vx0.w, vy0.w, sxy);

            sx += (vx1.x + vx1.y) + (vx1.z + vx1.w);
            sy += (vy1.x + vy1.y) + (vy1.z + vy1.w);
            sxx = fmaf(vx1.x, vx1.x, sxx); sxx = fmaf(vx1.y, vx1.y, sxx);
            sxx = fmaf(vx1.z, vx1.z, sxx); sxx = fmaf(vx1.w, vx1.w, sxx);
            syy = fmaf(vy1.x, vy1.x, syy); syy = fmaf(vy1.y, vy1.y, syy);
            syy = fmaf(vy1.z, vy1.z, syy); syy = fmaf(vy1.w, vy1.w, syy);
            sxy = fmaf(vx1.x, vy1.x, sxy); sxy = fmaf(vx1.y, vy1.y, sxy);
            sxy = fmaf(vx1.z, vy1.z, sxy); sxy = fmaf(vx1.w, vy1.w, sxy);
        }
    }

    // fold 4 adjacent threads (16 cols of one window, this row-half)
#pragma unroll
    for (int off = 1; off < 4; off <<= 1) {
        sx  += __shfl_xor_sync(0xffffffffu, sx,  off);
        sy  += __shfl_xor_sync(0xffffffffu, sy,  off);
        sxx += __shfl_xor_sync(0xffffffffu, sxx, off);
        syy += __shfl_xor_sync(0xffffffffu, syy, off);
        sxy += __shfl_xor_sync(0xffffffffu, sxy, off);
    }

    __shared__ float s_sums[2][NWIN_X][5];
    __shared__ unsigned int s_ticket;
    if ((t & 3) == 0) {
        const int win = t >> 2;
        s_sums[hh][win][0] = sx;
        s_sums[hh][win][1] = sy;
        s_sums[hh][win][2] = sxx;
        s_sums[hh][win][3] = syy;
        s_sums[hh][win][4] = sxy;
    }
    __syncthreads();

    if (tid < 32) {
        float S0 = s_sums[0][tid][0] + s_sums[1][tid][0];
        float S1 = s_sums[0][tid][1] + s_sums[1][tid][1];
        float S2 = s_sums[0][tid][2] + s_sums[1][tid][2];
        float S3 = s_sums[0][tid][3] + s_sums[1][tid][3];
        float S4 = s_sums[0][tid][4] + s_sums[1][tid][4];

        const float inv = 1.0f / (WS * WS);
        const float C1 = 6.5025f;
        const float C2 = 58.5225f;
        float mx = S0 * inv, my = S1 * inv;
        float vx = S2 * inv - mx * mx;
        float vy = S3 * inv - my * my;
        float cv = S4 * inv - mx * my;
        float num = (2.0f * mx * my + C1) * (2.0f * cv + C2);
        float den = (mx * mx + my * my + C1) * (vx + vy + C2);
        float v = num / den;

#pragma unroll
        for (int off = 16; off; off >>= 1)
            v += __shfl_xor_sync(0xffffffffu, v, off);
        if (tid == 0) {
            g_partial[blockIdx.x] = v;
            // release-scoped increment orders the partial store before the
            // ticket becomes visible; replaces __threadfence + relaxed atomic.
            s_ticket = atom_add_release(&g_ticket[b], 1u);
        }
    }
    __syncthreads();

    // Last CTA of this batch folds the 32 row-partials.
    if (s_ticket == NWIN_Y - 1) {
        if (tid < 32) {
            float v = ld_acquire_f32(&g_partial[b * NWIN_Y + tid]);
#pragma unroll
            for (int off = 16; off; off >>= 1)
                v += __shfl_xor_sync(0xffffffffu, v, off);
            if (tid == 0) {
                out[b] = (1.0f - v * (1.0f / (NWIN_X * NWIN_Y))) * 0.5f;
                g_ticket[b] = 0u;   // reset for next (graph-replayed) launch
            }
        }
    }
}

extern "C" void kernel_launch(void* const* d_in, const int* in_sizes, int n_in,
                              void* d_out, int out_size) {
    const float* x = (const float*)d_in[0];
    const float* y = (const float*)d_in[1];
    float* out = (float*)d_out;
    (void)in_sizes; (void)n_in; (void)out_size;

    ssim_fused_kernel<<<NBATCH * NWIN_Y, 256>>>(x, y, out);
}

// round 9
// speedup vs baseline: 1.0183x; 1.0110x over previous
#include <cuda_runtime.h>

// SSIM-style loss (sum over channels+window, /ws^2), single fused kernel.
// x, y: (32, 3, 512, 512) fp32. out: (32,) fp32.
//
// R9: finer CTA decomposition. Grid 2048 = (batch, window-row, col-half);
// 128 threads = (row-half hh, float4-col t within the 64-wide half).
// Each thread streams 8 rows x 3 channels (24 LDG.128 per input).
// 14 CTA/SM (one wave: 148*14=2072 >= 2048), 56 warps/SM -> 2x more
// independent DRAM streams per SM, half the straggler-tail granularity.
// Every 16x16 window is fully inside one CTA; ticket counts 64 CTAs/batch.

#define IMG_H 512
#define IMG_W 512
#define NCH 3
#define WS 16
#define NWIN_X 32
#define NWIN_Y 32
#define NBATCH 32
#define W4 (IMG_W / 4)
#define CTAS_PER_BATCH (NWIN_Y * 2)     // 64

static __device__ float        g_partial[NBATCH * CTAS_PER_BATCH];
static __device__ unsigned int g_ticket[NBATCH];

__global__ __launch_bounds__(128, 14)
void ssim_fused_kernel(const float* __restrict__ x, const float* __restrict__ y,
                       float* __restrict__ out) {
    const int tid = threadIdx.x;
    const int hh  = tid >> 6;              // row half: rows 0..7 / 8..15
    const int t   = tid & 63;              // float4 col within half, 0..63
    const int ch  = blockIdx.x & 1;        // column half
    const int br  = (blockIdx.x >> 1) & 31;// window row
    const int b   = blockIdx.x >> 6;       // batch

    const size_t img = (size_t)NCH * IMG_H * IMG_W;
    const float4* __restrict__ xp = (const float4*)(x + (size_t)b * img);
    const float4* __restrict__ yp = (const float4*)(y + (size_t)b * img);

    const int col4 = (ch << 6) + t;        // global float4 column 0..127

    float sx = 0.f, sy = 0.f, sxx = 0.f, syy = 0.f, sxy = 0.f;

#pragma unroll
    for (int c = 0; c < NCH; ++c) {
        size_t base = (size_t)c * (IMG_H * W4)
                    + (size_t)(br * WS + hh * 8) * W4 + col4;
#pragma unroll
        for (int h0 = 0; h0 < 8; h0 += 2) {
            float4 vx0 = __ldcs(xp + base + (size_t)(h0    ) * W4);
            float4 vx1 = __ldcs(xp + base + (size_t)(h0 + 1) * W4);
            float4 vy0 = __ldcs(yp + base + (size_t)(h0    ) * W4);
            float4 vy1 = __ldcs(yp + base + (size_t)(h0 + 1) * W4);

            sx += (vx0.x + vx0.y) + (vx0.z + vx0.w);
            sy += (vy0.x + vy0.y) + (vy0.z + vy0.w);
            sxx = fmaf(vx0.x, vx0.x, sxx); sxx = fmaf(vx0.y, vx0.y, sxx);
            sxx = fmaf(vx0.z, vx0.z, sxx); sxx = fmaf(vx0.w, vx0.w, sxx);
            syy = fmaf(vy0.x, vy0.x, syy); syy = fmaf(vy0.y, vy0.y, syy);
            syy = fmaf(vy0.z, vy0.z, syy); syy = fmaf(vy0.w, vy0.w, syy);
            sxy = fmaf(vx0.x, vy0.x, sxy); sxy = fmaf(vx0.y, vy0.y, sxy);
            sxy = fmaf(vx0.z, vy0.z, sxy); sxy = fmaf(vx0.w, vy0.w, sxy);

            sx += (vx1.x + vx1.y) + (vx1.z + vx1.w);
            sy += (vy1.x + vy1.y) + (vy1.z + vy1.w);
            sxx = fmaf(vx1.x, vx1.x, sxx); sxx = fmaf(vx1.y, vx1.y, sxx);
            sxx = fmaf(vx1.z, vx1.z, sxx); sxx = fmaf(vx1.w, vx1.w, sxx);
            syy = fmaf(vy1.x, vy1.x, syy); syy = fmaf(vy1.y, vy1.y, syy);
            syy = fmaf(vy1.z, vy1.z, syy); syy = fmaf(vy1.w, vy1.w, syy);
            sxy = fmaf(vx1.x, vy1.x, sxy); sxy = fmaf(vx1.y, vy1.y, sxy);
            sxy = fmaf(vx1.z, vy1.z, sxy); sxy = fmaf(vx1.w, vy1.w, sxy);
        }
    }

    // fold 4 adjacent threads (16 cols = one window, this row-half)
#pragma unroll
    for (int off = 1; off < 4; off <<= 1) {
        sx  += __shfl_xor_sync(0xffffffffu, sx,  off);
        sy  += __shfl_xor_sync(0xffffffffu, sy,  off);
        sxx += __shfl_xor_sync(0xffffffffu, sxx, off);
        syy += __shfl_xor_sync(0xffffffffu, syy, off);
        sxy += __shfl_xor_sync(0xffffffffu, sxy, off);
    }

    __shared__ float s_sums[2][16][5];     // [row-half][window-in-half][stat]
    __shared__ unsigned int s_ticket;
    if ((t & 3) == 0) {
        const int win = t >> 2;            // 0..15
        s_sums[hh][win][0] = sx;
        s_sums[hh][win][1] = sy;
        s_sums[hh][win][2] = sxx;
        s_sums[hh][win][3] = syy;
        s_sums[hh][win][4] = sxy;
    }
    __syncthreads();

    if (tid < 16) {
        float S0 = s_sums[0][tid][0] + s_sums[1][tid][0];
        float S1 = s_sums[0][tid][1] + s_sums[1][tid][1];
        float S2 = s_sums[0][tid][2] + s_sums[1][tid][2];
        float S3 = s_sums[0][tid][3] + s_sums[1][tid][3];
        float S4 = s_sums[0][tid][4] + s_sums[1][tid][4];

        const float inv = 1.0f / (WS * WS);
        const float C1 = 6.5025f;
        const float C2 = 58.5225f;
        float mx = S0 * inv, my = S1 * inv;
        float vx = S2 * inv - mx * mx;
        float vy = S3 * inv - my * my;
        float cv = S4 * inv - mx * my;
        float num = (2.0f * mx * my + C1) * (2.0f * cv + C2);
        float den = (mx * mx + my * my + C1) * (vx + vy + C2);
        float v = num / den;

#pragma unroll
        for (int off = 8; off; off >>= 1)
            v += __shfl_xor_sync(0x0000ffffu, v, off);
        if (tid == 0) {
            g_partial[blockIdx.x] = v;
            __threadfence();
            unsigned int tk = atomicAdd(&g_ticket[b], 1u);
            s_ticket = tk;
        }
    }
    __syncthreads();

    // Last CTA of this batch folds the 64 partials.
    if (s_ticket == CTAS_PER_BATCH - 1) {
        if (tid < 32) {
            volatile float* vp = (volatile float*)&g_partial[b * CTAS_PER_BATCH];
            float v = vp[tid] + vp[tid + 32];
#pragma unroll
            for (int off = 16; off; off >>= 1)
                v += __shfl_xor_sync(0xffffffffu, v, off);
            if (tid == 0) {
                out[b] = (1.0f - v * (1.0f / (NWIN_X * NWIN_Y))) * 0.5f;
                g_ticket[b] = 0u;   // reset for next (graph-replayed) launch
            }
        }
    }
}

extern "C" void kernel_launch(void* const* d_in, const int* in_sizes, int n_in,
                              void* d_out, int out_size) {
    const float* x = (const float*)d_in[0];
    const float* y = (const float*)d_in[1];
    float* out = (float*)d_out;
    (void)in_sizes; (void)n_in; (void)out_size;

    ssim_fused_kernel<<<NBATCH * CTAS_PER_BATCH, 128>>>(x, y, out);
}